// round 1
// baseline (speedup 1.0000x reference)
#include <cuda_runtime.h>
#include <cstdint>

#define N_NODES 100000
#define N_EDGES 1600000
#define C_IN 256
#define C_HID 128
#define C_OUT 64
#define SCAN_BLOCKS 98   // ceil(100000/1024)

// ---------------- scratch (static device globals; no allocation) -------------
__device__ float g_y[(size_t)N_NODES * 256];   // per-layer GEMM output [yl | yr]
__device__ float g_h1[(size_t)N_NODES * 128];  // relu(layer0 out)
__device__ int   g_deg[N_NODES];
__device__ int   g_fill[N_NODES];
__device__ int   g_rowptr[N_NODES + 1];
__device__ int   g_csr[N_EDGES];
__device__ int   g_bsums[SCAN_BLOCKS];

// ---------------- CSR build --------------------------------------------------
__global__ void zero_kernel() {
    int i = blockIdx.x * blockDim.x + threadIdx.x;
    if (i < N_NODES) { g_deg[i] = 0; g_fill[i] = 0; }
}

__global__ void deg_kernel(const int* __restrict__ dst) {
    int e = blockIdx.x * blockDim.x + threadIdx.x;
    if (e < N_EDGES) atomicAdd(&g_deg[dst[e]], 1);
}

__global__ void scan1_kernel() {
    __shared__ int s[1024];
    int tid = threadIdx.x;
    int idx = blockIdx.x * 1024 + tid;
    int v = (idx < N_NODES) ? g_deg[idx] : 0;
    s[tid] = v;
    __syncthreads();
    for (int off = 1; off < 1024; off <<= 1) {
        int t = 0;
        if (tid >= off) t = s[tid - off];
        __syncthreads();
        s[tid] += t;
        __syncthreads();
    }
    if (idx < N_NODES) g_rowptr[idx + 1] = s[tid];
    if (tid == 1023) g_bsums[blockIdx.x] = s[tid];
    if (idx == 0) g_rowptr[0] = 0;
}

__global__ void scan2_kernel() {
    if (threadIdx.x == 0 && blockIdx.x == 0) {
        int run = 0;
        for (int i = 0; i < SCAN_BLOCKS; i++) {
            int t = g_bsums[i];
            g_bsums[i] = run;
            run += t;
        }
    }
}

__global__ void scan3_kernel() {
    int idx = blockIdx.x * 1024 + threadIdx.x;
    if (idx < N_NODES) g_rowptr[idx + 1] += g_bsums[blockIdx.x];
}

__global__ void fill_kernel(const int* __restrict__ src, const int* __restrict__ dst) {
    int e = blockIdx.x * blockDim.x + threadIdx.x;
    if (e < N_EDGES) {
        int d = dst[e];
        int pos = g_rowptr[d] + atomicAdd(&g_fill[d], 1);
        g_csr[pos] = src[e];
    }
}

// ---------------- fp32 tiled GEMM: C[M,NB] = A[M,K] * B[K,NB] ---------------
// A row-major lda=K, B row-major ldb=NB, C row-major ldc (with column offset
// applied by caller via pointer). BM=128 BN=64 BK=16, 256 threads, 8x4/thread.
__global__ void __launch_bounds__(256)
gemm_kernel(const float* __restrict__ A, const float* __restrict__ B,
            float* __restrict__ C, int M, int K, int NB, int ldc) {
    __shared__ float As[16][132];
    __shared__ float Bs[16][64];
    int tid = threadIdx.x;
    int tr = tid >> 4;        // 0..15
    int tc = tid & 15;        // 0..15
    int rowBase = blockIdx.x * 128;
    int colBase = blockIdx.y * 64;

    float acc[8][4];
#pragma unroll
    for (int i = 0; i < 8; i++)
#pragma unroll
        for (int j = 0; j < 4; j++) acc[i][j] = 0.f;

    for (int k0 = 0; k0 < K; k0 += 16) {
        // A tile: 128x16 = 512 float4, 2 per thread
#pragma unroll
        for (int i = 0; i < 2; i++) {
            int lid = tid * 2 + i;
            int ar = lid >> 2;
            int ac = (lid & 3) * 4;
            int grow = rowBase + ar;
            float4 v = make_float4(0.f, 0.f, 0.f, 0.f);
            if (grow < M) v = *(const float4*)(A + (size_t)grow * K + k0 + ac);
            As[ac + 0][ar] = v.x;
            As[ac + 1][ar] = v.y;
            As[ac + 2][ar] = v.z;
            As[ac + 3][ar] = v.w;
        }
        // B tile: 16x64 = 256 float4, 1 per thread
        {
            int brow = tid >> 4;
            int bcol = (tid & 15) * 4;
            float4 v = *(const float4*)(B + (size_t)(k0 + brow) * NB + colBase + bcol);
            *(float4*)&Bs[brow][bcol] = v;
        }
        __syncthreads();
#pragma unroll
        for (int kk = 0; kk < 16; kk++) {
            float4 b4 = *(float4*)&Bs[kk][tc * 4];
            float a[8];
#pragma unroll
            for (int i = 0; i < 8; i++) a[i] = As[kk][tr * 8 + i];
#pragma unroll
            for (int i = 0; i < 8; i++) {
                acc[i][0] += a[i] * b4.x;
                acc[i][1] += a[i] * b4.y;
                acc[i][2] += a[i] * b4.z;
                acc[i][3] += a[i] * b4.w;
            }
        }
        __syncthreads();
    }
#pragma unroll
    for (int i = 0; i < 8; i++) {
        int grow = rowBase + tr * 8 + i;
        if (grow < M) {
            float4 v = make_float4(acc[i][0], acc[i][1], acc[i][2], acc[i][3]);
            *(float4*)(C + (size_t)grow * ldc + colBase + tc * 4) = v;
        }
    }
}

// ---------------- aggregation epilogue --------------------------------------
// y rows are [yl(C) | yr(C)]; out[i] = mean_{s in nbrs(i)} yl[s] + yr[i] + b
// one warp per node, float4 lanes (C=128) or float2 (C=64).
template <bool WPRE, bool WPOST>
__global__ void agg128_kernel(const float* __restrict__ y, const float* __restrict__ bias,
                              float* __restrict__ outPre, float* __restrict__ outPost) {
    int warp = (blockIdx.x * blockDim.x + threadIdx.x) >> 5;
    int lane = threadIdx.x & 31;
    if (warp >= N_NODES) return;
    int beg = g_rowptr[warp], end = g_rowptr[warp + 1];
    float ax = 0.f, ay = 0.f, az = 0.f, aw = 0.f;
    int e = beg;
    for (; e + 4 <= end; e += 4) {
        int s0 = g_csr[e], s1 = g_csr[e + 1], s2 = g_csr[e + 2], s3 = g_csr[e + 3];
        float4 r0 = *(const float4*)(y + (size_t)s0 * 256 + lane * 4);
        float4 r1 = *(const float4*)(y + (size_t)s1 * 256 + lane * 4);
        float4 r2 = *(const float4*)(y + (size_t)s2 * 256 + lane * 4);
        float4 r3 = *(const float4*)(y + (size_t)s3 * 256 + lane * 4);
        ax += r0.x + r1.x + r2.x + r3.x;
        ay += r0.y + r1.y + r2.y + r3.y;
        az += r0.z + r1.z + r2.z + r3.z;
        aw += r0.w + r1.w + r2.w + r3.w;
    }
    for (; e < end; e++) {
        int s = g_csr[e];
        float4 r = *(const float4*)(y + (size_t)s * 256 + lane * 4);
        ax += r.x; ay += r.y; az += r.z; aw += r.w;
    }
    int deg = end - beg;
    float inv = 1.f / (float)(deg > 0 ? deg : 1);
    float4 yr = *(const float4*)(y + (size_t)warp * 256 + 128 + lane * 4);
    float4 b  = *(const float4*)(bias + lane * 4);
    float v0 = ax * inv + yr.x + b.x;
    float v1 = ay * inv + yr.y + b.y;
    float v2 = az * inv + yr.z + b.z;
    float v3 = aw * inv + yr.w + b.w;
    size_t o = (size_t)warp * 128 + lane * 4;
    if (WPRE)  *(float4*)(outPre + o)  = make_float4(v0, v1, v2, v3);
    if (WPOST) *(float4*)(outPost + o) = make_float4(fmaxf(v0, 0.f), fmaxf(v1, 0.f),
                                                     fmaxf(v2, 0.f), fmaxf(v3, 0.f));
}

__global__ void agg64_kernel(const float* __restrict__ y, const float* __restrict__ bias,
                             float* __restrict__ outPre) {
    int warp = (blockIdx.x * blockDim.x + threadIdx.x) >> 5;
    int lane = threadIdx.x & 31;
    if (warp >= N_NODES) return;
    int beg = g_rowptr[warp], end = g_rowptr[warp + 1];
    float ax = 0.f, ay = 0.f;
    int e = beg;
    for (; e + 4 <= end; e += 4) {
        int s0 = g_csr[e], s1 = g_csr[e + 1], s2 = g_csr[e + 2], s3 = g_csr[e + 3];
        float2 r0 = *(const float2*)(y + (size_t)s0 * 128 + lane * 2);
        float2 r1 = *(const float2*)(y + (size_t)s1 * 128 + lane * 2);
        float2 r2 = *(const float2*)(y + (size_t)s2 * 128 + lane * 2);
        float2 r3 = *(const float2*)(y + (size_t)s3 * 128 + lane * 2);
        ax += r0.x + r1.x + r2.x + r3.x;
        ay += r0.y + r1.y + r2.y + r3.y;
    }
    for (; e < end; e++) {
        int s = g_csr[e];
        float2 r = *(const float2*)(y + (size_t)s * 128 + lane * 2);
        ax += r.x; ay += r.y;
    }
    int deg = end - beg;
    float inv = 1.f / (float)(deg > 0 ? deg : 1);
    float2 yr = *(const float2*)(y + (size_t)warp * 128 + 64 + lane * 2);
    float2 b  = *(const float2*)(bias + lane * 2);
    float v0 = ax * inv + yr.x + b.x;
    float v1 = ay * inv + yr.y + b.y;
    *(float2*)(outPre + (size_t)warp * 64 + lane * 2) = make_float2(v0, v1);
}

// ---------------- host launch ------------------------------------------------
static void run_gemm(const float* A, const float* B, float* C, int M, int K, int NB, int ldc) {
    dim3 grid((M + 127) / 128, (NB + 63) / 64);
    gemm_kernel<<<grid, 256>>>(A, B, C, M, K, NB, ldc);
}

extern "C" void kernel_launch(void* const* d_in, const int* in_sizes, int n_in,
                              void* d_out, int out_size) {
    const float* x   = (const float*)d_in[0];
    const int*   ei  = (const int*)d_in[1];
    const float* Wl0 = (const float*)d_in[2];
    const float* Wr0 = (const float*)d_in[3];
    const float* b0  = (const float*)d_in[4];
    const float* Wl1 = (const float*)d_in[5];
    const float* Wr1 = (const float*)d_in[6];
    const float* b1  = (const float*)d_in[7];
    const float* Wl2 = (const float*)d_in[8];
    const float* Wr2 = (const float*)d_in[9];
    const float* b2  = (const float*)d_in[10];

    const int* src = ei;
    const int* dst = ei + N_EDGES;

    float* out_final = (float*)d_out;                       // [N,64]
    float* out_pre1  = out_final + (size_t)N_NODES * 64;    // [N,128] pre-relu layer1
    float* out_g     = out_pre1 + (size_t)N_NODES * 128;    // [N,128] relu(layer1)

    float* yptr;  float* h1ptr;
    cudaGetSymbolAddress((void**)&yptr, g_y);
    cudaGetSymbolAddress((void**)&h1ptr, g_h1);

    // CSR build
    zero_kernel<<<(N_NODES + 1023) / 1024, 1024>>>();
    deg_kernel<<<(N_EDGES + 255) / 256, 256>>>(dst);
    scan1_kernel<<<SCAN_BLOCKS, 1024>>>();
    scan2_kernel<<<1, 32>>>();
    scan3_kernel<<<SCAN_BLOCKS, 1024>>>();
    fill_kernel<<<(N_EDGES + 255) / 256, 256>>>(src, dst);

    const int aggGrid = (N_NODES * 32 + 255) / 256;

    // Layer 0: y = [x@Wl0 | x@Wr0]; h1 = relu(agg + yr + b0)
    run_gemm(x, Wl0, yptr,       N_NODES, 256, 128, 256);
    run_gemm(x, Wr0, yptr + 128, N_NODES, 256, 128, 256);
    agg128_kernel<false, true><<<aggGrid, 256>>>(yptr, b0, nullptr, h1ptr);

    // Layer 1: out_pre1 = agg + yr + b1; g = relu(out_pre1)
    run_gemm(h1ptr, Wl1, yptr,       N_NODES, 128, 128, 256);
    run_gemm(h1ptr, Wr1, yptr + 128, N_NODES, 128, 128, 256);
    agg128_kernel<true, true><<<aggGrid, 256>>>(yptr, b1, out_pre1, out_g);

    // Layer 2: x_final = agg + yr + b2 (no relu)
    run_gemm(out_g, Wl2, yptr,      N_NODES, 128, 64, 128);
    run_gemm(out_g, Wr2, yptr + 64, N_NODES, 128, 64, 128);
    agg64_kernel<<<aggGrid, 256>>>(yptr, b2, out_final);
}

// round 5
// speedup vs baseline: 1.7837x; 1.7837x over previous
#include <cuda_runtime.h>
#include <cstdint>

#define N_NODES 100000
#define N_EDGES 1600000
#define SCAN_BLOCKS 98   // ceil(100000/1024)

// ====================== helpers =============================================
__device__ __forceinline__ float to_tf32(float x) {
    float y;
    asm("cvt.rna.tf32.f32 %0, %1;" : "=f"(y) : "f"(x));
    return y;
}

__device__ __forceinline__ void mma_tf32(float c[4], const uint32_t a[4], const uint32_t b[2]) {
    asm volatile(
        "mma.sync.aligned.m16n8k8.row.col.f32.tf32.tf32.f32 "
        "{%0,%1,%2,%3}, {%4,%5,%6,%7}, {%8,%9}, {%0,%1,%2,%3};"
        : "+f"(c[0]), "+f"(c[1]), "+f"(c[2]), "+f"(c[3])
        : "r"(a[0]), "r"(a[1]), "r"(a[2]), "r"(a[3]), "r"(b[0]), "r"(b[1]));
}

// ====================== scratch globals =====================================
__device__ float g_y[(size_t)N_NODES * 256];   // per-layer GEMM output [yl | yr]
__device__ float g_h1[(size_t)N_NODES * 128];  // relu(layer0 out)
__device__ int   g_deg[N_NODES];
__device__ int   g_fill[N_NODES];
__device__ int   g_rowptr[N_NODES + 1];
__device__ int   g_csr[N_EDGES];
__device__ int   g_bsums[SCAN_BLOCKS];
__device__ float g_wt0[256 * 256];   // [n][k]: n<128 -> Wl0[:,n], else Wr0[:,n-128]
__device__ float g_wt1[256 * 128];
__device__ float g_wt2[128 * 128];

// ====================== CSR build ===========================================
__global__ void zero_kernel() {
    int i = blockIdx.x * blockDim.x + threadIdx.x;
    if (i < N_NODES) { g_deg[i] = 0; g_fill[i] = 0; }
}
__global__ void deg_kernel(const int* __restrict__ dst) {
    int e = blockIdx.x * blockDim.x + threadIdx.x;
    if (e < N_EDGES) atomicAdd(&g_deg[dst[e]], 1);
}
__global__ void scan1_kernel() {
    __shared__ int s[1024];
    int tid = threadIdx.x;
    int idx = blockIdx.x * 1024 + tid;
    int v = (idx < N_NODES) ? g_deg[idx] : 0;
    s[tid] = v;
    __syncthreads();
    for (int off = 1; off < 1024; off <<= 1) {
        int t = 0;
        if (tid >= off) t = s[tid - off];
        __syncthreads();
        s[tid] += t;
        __syncthreads();
    }
    if (idx < N_NODES) g_rowptr[idx + 1] = s[tid];
    if (tid == 1023) g_bsums[blockIdx.x] = s[tid];
    if (idx == 0) g_rowptr[0] = 0;
}
__global__ void scan2_kernel() {       // 128-thread shfl scan over SCAN_BLOCKS sums
    int tid = threadIdx.x;
    int v = (tid < SCAN_BLOCKS) ? g_bsums[tid] : 0;
    int lane = tid & 31, w = tid >> 5;
    int x = v;
    for (int o = 1; o < 32; o <<= 1) {
        int t = __shfl_up_sync(0xFFFFFFFFu, x, o);
        if (lane >= o) x += t;
    }
    __shared__ int ws[4];
    if (lane == 31) ws[w] = x;
    __syncthreads();
    int add = 0;
    for (int i = 0; i < w; i++) add += ws[i];
    if (tid < SCAN_BLOCKS) g_bsums[tid] = x + add - v;  // exclusive
}
__global__ void scan3_kernel() {
    int idx = blockIdx.x * 1024 + threadIdx.x;
    if (idx < N_NODES) g_rowptr[idx + 1] += g_bsums[blockIdx.x];
}
__global__ void fill_kernel(const int* __restrict__ src, const int* __restrict__ dst) {
    int e = blockIdx.x * blockDim.x + threadIdx.x;
    if (e < N_EDGES) {
        int d = dst[e];
        int pos = g_rowptr[d] + atomicAdd(&g_fill[d], 1);
        g_csr[pos] = src[e];
    }
}

// ====================== weight pre-transpose ================================
__global__ void wtrans_kernel(const float* __restrict__ Wl0, const float* __restrict__ Wr0,
                              const float* __restrict__ Wl1, const float* __restrict__ Wr1,
                              const float* __restrict__ Wl2, const float* __restrict__ Wr2) {
    int i = blockIdx.x * blockDim.x + threadIdx.x;
    if (i < 256 * 256) {                       // wt0: N=256, K=256
        int n = i >> 8, k = i & 255;
        g_wt0[i] = (n < 128) ? Wl0[k * 128 + n] : Wr0[k * 128 + (n - 128)];
    }
    if (i < 256 * 128) {                       // wt1: N=256, K=128
        int n = i >> 7, k = i & 127;
        g_wt1[i] = (n < 128) ? Wl1[k * 128 + n] : Wr1[k * 128 + (n - 128)];
    }
    if (i < 128 * 128) {                       // wt2: N=128, K=128
        int n = i >> 7, k = i & 127;
        g_wt2[i] = (n < 64) ? Wl2[k * 64 + n] : Wr2[k * 64 + (n - 64)];
    }
}

// ====================== mma.sync tf32 GEMM ==================================
// C[M, LDC] tile: 128 rows x 128 cols per CTA (blockIdx.y selects col tile).
// A row-major [M, KT]; BT row-major [NN, KT] (C[m][n] = sum_k A[m][k]*BT[n][k]).
// 8 warps: warpM = wid&3 (32 rows), warpN = wid>>2 (64 cols).
// K chunked KC=32 in SMEM, double-buffered via register prefetch.
#define KC 32
#define SM_STRIDE 36                        // floats; (4r+k)%32 covers all banks
#define BUF_FLOATS (128 * SM_STRIDE)        // 4608 per matrix
#define STAGE_FLOATS (2 * BUF_FLOATS)       // A + B per stage

template <int KT, int LDC>
__global__ void __launch_bounds__(256, 1)
gemm_mma_kernel(const float* __restrict__ A, const float* __restrict__ BT,
                float* __restrict__ C, int M) {
    extern __shared__ float sm[];
    const int tid = threadIdx.x;
    const int wid = tid >> 5;
    const int lane = tid & 31;
    const int warpM = wid & 3;
    const int warpN = wid >> 2;
    const int rowBase = blockIdx.x * 128;
    const int colBase = blockIdx.y * 128;
    constexpr int NC = KT / KC;

    float acc[2][8][4];
#pragma unroll
    for (int mt = 0; mt < 2; mt++)
#pragma unroll
        for (int nt = 0; nt < 8; nt++)
#pragma unroll
            for (int q = 0; q < 4; q++) acc[mt][nt][q] = 0.f;

    // prefetch indices: each thread loads 4 float4 of A and 4 of B per chunk
    const int ldRow = tid >> 3;          // 0..31 (+i*32)
    const int ldKq  = (tid & 7) * 4;     // k offset in floats

    float4 ra[4], rb[4];
    // ---- load chunk 0 ----
#pragma unroll
    for (int i = 0; i < 4; i++) {
        int r = ldRow + i * 32;
        int gr = rowBase + r;
        ra[i] = (gr < M) ? *(const float4*)(A + (size_t)gr * KT + ldKq)
                         : make_float4(0.f, 0.f, 0.f, 0.f);
        int gn = colBase + r;
        rb[i] = *(const float4*)(BT + (size_t)gn * KT + ldKq);
    }
    // store chunk 0 to stage 0 (with tf32 rounding)
    {
        float* As = sm;
        float* Bs = sm + BUF_FLOATS;
#pragma unroll
        for (int i = 0; i < 4; i++) {
            int r = ldRow + i * 32;
            float4 va = ra[i], vb = rb[i];
            va.x = to_tf32(va.x); va.y = to_tf32(va.y); va.z = to_tf32(va.z); va.w = to_tf32(va.w);
            vb.x = to_tf32(vb.x); vb.y = to_tf32(vb.y); vb.z = to_tf32(vb.z); vb.w = to_tf32(vb.w);
            *(float4*)(As + r * SM_STRIDE + ldKq) = va;
            *(float4*)(Bs + r * SM_STRIDE + ldKq) = vb;
        }
    }
    __syncthreads();

    const int aRow = warpM * 32 + (lane >> 2);
    const int aCol = lane & 3;
    const int bRow = warpN * 64 + (lane >> 2);

    for (int c = 0; c < NC; c++) {
        // ---- prefetch next chunk into regs ----
        if (c + 1 < NC) {
            int kBase = (c + 1) * KC;
#pragma unroll
            for (int i = 0; i < 4; i++) {
                int r = ldRow + i * 32;
                int gr = rowBase + r;
                ra[i] = (gr < M) ? *(const float4*)(A + (size_t)gr * KT + kBase + ldKq)
                                 : make_float4(0.f, 0.f, 0.f, 0.f);
                int gn = colBase + r;
                rb[i] = *(const float4*)(BT + (size_t)gn * KT + kBase + ldKq);
            }
        }
        // ---- compute from stage c&1 ----
        const float* As = sm + (c & 1) * STAGE_FLOATS;
        const float* Bs = As + BUF_FLOATS;
#pragma unroll
        for (int ks = 0; ks < KC / 8; ks++) {
            uint32_t af[2][4];
            uint32_t bf[8][2];
#pragma unroll
            for (int mt = 0; mt < 2; mt++) {
                const float* p = As + (aRow + mt * 16) * SM_STRIDE + ks * 8 + aCol;
                af[mt][0] = __float_as_uint(p[0]);
                af[mt][1] = __float_as_uint(p[8 * SM_STRIDE]);
                af[mt][2] = __float_as_uint(p[4]);
                af[mt][3] = __float_as_uint(p[8 * SM_STRIDE + 4]);
            }
#pragma unroll
            for (int nt = 0; nt < 8; nt++) {
                const float* p = Bs + (bRow + nt * 8) * SM_STRIDE + ks * 8 + aCol;
                bf[nt][0] = __float_as_uint(p[0]);
                bf[nt][1] = __float_as_uint(p[4]);
            }
#pragma unroll
            for (int mt = 0; mt < 2; mt++)
#pragma unroll
                for (int nt = 0; nt < 8; nt++)
                    mma_tf32(acc[mt][nt], af[mt], bf[nt]);
        }
        // ---- store prefetched chunk to other stage ----
        if (c + 1 < NC) {
            float* Asn = sm + ((c + 1) & 1) * STAGE_FLOATS;
            float* Bsn = Asn + BUF_FLOATS;
#pragma unroll
            for (int i = 0; i < 4; i++) {
                int r = ldRow + i * 32;
                float4 va = ra[i], vb = rb[i];
                va.x = to_tf32(va.x); va.y = to_tf32(va.y); va.z = to_tf32(va.z); va.w = to_tf32(va.w);
                vb.x = to_tf32(vb.x); vb.y = to_tf32(vb.y); vb.z = to_tf32(vb.z); vb.w = to_tf32(vb.w);
                *(float4*)(Asn + r * SM_STRIDE + ldKq) = va;
                *(float4*)(Bsn + r * SM_STRIDE + ldKq) = vb;
            }
            __syncthreads();
        }
    }

    // ---- epilogue: write C ----
#pragma unroll
    for (int mt = 0; mt < 2; mt++) {
        int r0 = rowBase + warpM * 32 + mt * 16 + (lane >> 2);
#pragma unroll
        for (int nt = 0; nt < 8; nt++) {
            int col = colBase + warpN * 64 + nt * 8 + (lane & 3) * 2;
            if (r0 < M)
                *(float2*)(C + (size_t)r0 * LDC + col) = make_float2(acc[mt][nt][0], acc[mt][nt][1]);
            if (r0 + 8 < M)
                *(float2*)(C + (size_t)(r0 + 8) * LDC + col) = make_float2(acc[mt][nt][2], acc[mt][nt][3]);
        }
    }
}

// ====================== aggregation epilogue ================================
template <bool WPRE, bool WPOST>
__global__ void agg128_kernel(const float* __restrict__ y, const float* __restrict__ bias,
                              float* __restrict__ outPre, float* __restrict__ outPost) {
    int warp = (blockIdx.x * blockDim.x + threadIdx.x) >> 5;
    int lane = threadIdx.x & 31;
    if (warp >= N_NODES) return;
    int beg = g_rowptr[warp], end = g_rowptr[warp + 1];
    float ax = 0.f, ay = 0.f, az = 0.f, aw = 0.f;
    int e = beg;
    for (; e + 4 <= end; e += 4) {
        int s0 = g_csr[e], s1 = g_csr[e + 1], s2 = g_csr[e + 2], s3 = g_csr[e + 3];
        float4 r0 = *(const float4*)(y + (size_t)s0 * 256 + lane * 4);
        float4 r1 = *(const float4*)(y + (size_t)s1 * 256 + lane * 4);
        float4 r2 = *(const float4*)(y + (size_t)s2 * 256 + lane * 4);
        float4 r3 = *(const float4*)(y + (size_t)s3 * 256 + lane * 4);
        ax += r0.x + r1.x + r2.x + r3.x;
        ay += r0.y + r1.y + r2.y + r3.y;
        az += r0.z + r1.z + r2.z + r3.z;
        aw += r0.w + r1.w + r2.w + r3.w;
    }
    for (; e < end; e++) {
        int s = g_csr[e];
        float4 r = *(const float4*)(y + (size_t)s * 256 + lane * 4);
        ax += r.x; ay += r.y; az += r.z; aw += r.w;
    }
    int deg = end - beg;
    float inv = 1.f / (float)(deg > 0 ? deg : 1);
    float4 yr = *(const float4*)(y + (size_t)warp * 256 + 128 + lane * 4);
    float4 b  = *(const float4*)(bias + lane * 4);
    float v0 = ax * inv + yr.x + b.x;
    float v1 = ay * inv + yr.y + b.y;
    float v2 = az * inv + yr.z + b.z;
    float v3 = aw * inv + yr.w + b.w;
    size_t o = (size_t)warp * 128 + lane * 4;
    if (WPRE)  *(float4*)(outPre + o)  = make_float4(v0, v1, v2, v3);
    if (WPOST) *(float4*)(outPost + o) = make_float4(fmaxf(v0, 0.f), fmaxf(v1, 0.f),
                                                     fmaxf(v2, 0.f), fmaxf(v3, 0.f));
}

__global__ void agg64_kernel(const float* __restrict__ y, const float* __restrict__ bias,
                             float* __restrict__ outPre) {
    int warp = (blockIdx.x * blockDim.x + threadIdx.x) >> 5;
    int lane = threadIdx.x & 31;
    if (warp >= N_NODES) return;
    int beg = g_rowptr[warp], end = g_rowptr[warp + 1];
    float ax = 0.f, ay = 0.f;
    int e = beg;
    for (; e + 4 <= end; e += 4) {
        int s0 = g_csr[e], s1 = g_csr[e + 1], s2 = g_csr[e + 2], s3 = g_csr[e + 3];
        float2 r0 = *(const float2*)(y + (size_t)s0 * 128 + lane * 2);
        float2 r1 = *(const float2*)(y + (size_t)s1 * 128 + lane * 2);
        float2 r2 = *(const float2*)(y + (size_t)s2 * 128 + lane * 2);
        float2 r3 = *(const float2*)(y + (size_t)s3 * 128 + lane * 2);
        ax += r0.x + r1.x + r2.x + r3.x;
        ay += r0.y + r1.y + r2.y + r3.y;
    }
    for (; e < end; e++) {
        int s = g_csr[e];
        float2 r = *(const float2*)(y + (size_t)s * 128 + lane * 2);
        ax += r.x; ay += r.y;
    }
    int deg = end - beg;
    float inv = 1.f / (float)(deg > 0 ? deg : 1);
    float2 yr = *(const float2*)(y + (size_t)warp * 128 + 64 + lane * 2);
    float2 b  = *(const float2*)(bias + lane * 2);
    float v0 = ax * inv + yr.x + b.x;
    float v1 = ay * inv + yr.y + b.y;
    *(float2*)(outPre + (size_t)warp * 64 + lane * 2) = make_float2(v0, v1);
}

// ====================== host launch =========================================
extern "C" void kernel_launch(void* const* d_in, const int* in_sizes, int n_in,
                              void* d_out, int out_size) {
    const float* x   = (const float*)d_in[0];
    const int*   ei  = (const int*)d_in[1];
    const float* Wl0 = (const float*)d_in[2];
    const float* Wr0 = (const float*)d_in[3];
    const float* b0  = (const float*)d_in[4];
    const float* Wl1 = (const float*)d_in[5];
    const float* Wr1 = (const float*)d_in[6];
    const float* b1  = (const float*)d_in[7];
    const float* Wl2 = (const float*)d_in[8];
    const float* Wr2 = (const float*)d_in[9];
    const float* b2  = (const float*)d_in[10];

    const int* src = ei;
    const int* dst = ei + N_EDGES;

    float* out_final = (float*)d_out;                       // [N,64]
    float* out_pre1  = out_final + (size_t)N_NODES * 64;    // [N,128] pre-relu layer1
    float* out_g     = out_pre1 + (size_t)N_NODES * 128;    // [N,128] relu(layer1)

    float *yptr, *h1ptr, *wt0, *wt1, *wt2;
    cudaGetSymbolAddress((void**)&yptr, g_y);
    cudaGetSymbolAddress((void**)&h1ptr, g_h1);
    cudaGetSymbolAddress((void**)&wt0, g_wt0);
    cudaGetSymbolAddress((void**)&wt1, g_wt1);
    cudaGetSymbolAddress((void**)&wt2, g_wt2);

    constexpr int SMEM_GEMM = 2 * STAGE_FLOATS * 4;   // 73728 bytes
    cudaFuncSetAttribute(gemm_mma_kernel<256, 256>,
                         cudaFuncAttributeMaxDynamicSharedMemorySize, SMEM_GEMM);
    cudaFuncSetAttribute(gemm_mma_kernel<128, 256>,
                         cudaFuncAttributeMaxDynamicSharedMemorySize, SMEM_GEMM);
    cudaFuncSetAttribute(gemm_mma_kernel<128, 128>,
                         cudaFuncAttributeMaxDynamicSharedMemorySize, SMEM_GEMM);

    // CSR build + weight transpose
    zero_kernel<<<(N_NODES + 1023) / 1024, 1024>>>();
    deg_kernel<<<(N_EDGES + 255) / 256, 256>>>(dst);
    scan1_kernel<<<SCAN_BLOCKS, 1024>>>();
    scan2_kernel<<<1, 128>>>();
    scan3_kernel<<<SCAN_BLOCKS, 1024>>>();
    fill_kernel<<<(N_EDGES + 255) / 256, 256>>>(src, dst);
    wtrans_kernel<<<(256 * 256 + 255) / 256, 256>>>(Wl0, Wr0, Wl1, Wr1, Wl2, Wr2);

    const int aggGrid = (N_NODES * 32 + 255) / 256;
    const int gemmGridX = (N_NODES + 127) / 128;   // 782

    // Layer 0: y = [x@Wl0 | x@Wr0]; h1 = relu(agg + yr + b0)
    gemm_mma_kernel<256, 256><<<dim3(gemmGridX, 2), 256, SMEM_GEMM>>>(x, wt0, yptr, N_NODES);
    agg128_kernel<false, true><<<aggGrid, 256>>>(yptr, b0, nullptr, h1ptr);

    // Layer 1: out_pre1 = agg + yr + b1; g = relu(out_pre1)
    gemm_mma_kernel<128, 256><<<dim3(gemmGridX, 2), 256, SMEM_GEMM>>>(h1ptr, wt1, yptr, N_NODES);
    agg128_kernel<true, true><<<aggGrid, 256>>>(yptr, b1, out_pre1, out_g);

    // Layer 2: x_final = agg + yr + b2 (no relu)
    gemm_mma_kernel<128, 128><<<dim3(gemmGridX, 1), 256, SMEM_GEMM>>>(out_g, wt2, yptr, N_NODES);
    agg64_kernel<<<aggGrid, 256>>>(yptr, b2, out_final);
}

// round 6
// speedup vs baseline: 1.9513x; 1.0940x over previous
#include <cuda_runtime.h>
#include <cuda_fp16.h>
#include <cstdint>

#define N_NODES 100000
#define N_EDGES 1600000
#define SCAN_BLOCKS 98   // ceil(100000/1024)

// ====================== helpers =============================================
__device__ __forceinline__ float to_tf32(float x) {
    float y;
    asm("cvt.rna.tf32.f32 %0, %1;" : "=f"(y) : "f"(x));
    return y;
}

__device__ __forceinline__ void mma_tf32(float c[4], const uint32_t a[4], const uint32_t b[2]) {
    asm volatile(
        "mma.sync.aligned.m16n8k8.row.col.f32.tf32.tf32.f32 "
        "{%0,%1,%2,%3}, {%4,%5,%6,%7}, {%8,%9}, {%0,%1,%2,%3};"
        : "+f"(c[0]), "+f"(c[1]), "+f"(c[2]), "+f"(c[3])
        : "r"(a[0]), "r"(a[1]), "r"(a[2]), "r"(a[3]), "r"(b[0]), "r"(b[1]));
}

// ====================== scratch globals =====================================
__device__ __half g_ylh[(size_t)N_NODES * 128];  // yl half (fp16, gathered side)
__device__ float  g_yr[(size_t)N_NODES * 128];   // yr half (fp32, exact side)
__device__ float  g_h1[(size_t)N_NODES * 128];   // relu(layer0 out)
__device__ int    g_deg[N_NODES];
__device__ int    g_fill[N_NODES];
__device__ int    g_rowptr[N_NODES + 1];
__device__ int    g_csr[N_EDGES];
__device__ int    g_bsums[SCAN_BLOCKS];
__device__ float  g_wt0[256 * 256];   // [n][k]: n<128 -> Wl0[:,n], else Wr0[:,n-128]
__device__ float  g_wt1[256 * 128];
__device__ float  g_wt2[128 * 128];

// ====================== CSR build ===========================================
__global__ void zero_kernel() {
    int i = blockIdx.x * blockDim.x + threadIdx.x;
    if (i < N_NODES) { g_deg[i] = 0; g_fill[i] = 0; }
}
__global__ void deg_kernel(const int* __restrict__ dst) {
    int e = blockIdx.x * blockDim.x + threadIdx.x;
    if (e < N_EDGES) atomicAdd(&g_deg[dst[e]], 1);
}
__global__ void scan1_kernel() {
    __shared__ int s[1024];
    int tid = threadIdx.x;
    int idx = blockIdx.x * 1024 + tid;
    int v = (idx < N_NODES) ? g_deg[idx] : 0;
    s[tid] = v;
    __syncthreads();
    for (int off = 1; off < 1024; off <<= 1) {
        int t = 0;
        if (tid >= off) t = s[tid - off];
        __syncthreads();
        s[tid] += t;
        __syncthreads();
    }
    if (idx < N_NODES) g_rowptr[idx + 1] = s[tid];
    if (tid == 1023) g_bsums[blockIdx.x] = s[tid];
    if (idx == 0) g_rowptr[0] = 0;
}
__global__ void scan2_kernel() {       // 128-thread shfl scan over SCAN_BLOCKS sums
    int tid = threadIdx.x;
    int v = (tid < SCAN_BLOCKS) ? g_bsums[tid] : 0;
    int lane = tid & 31, w = tid >> 5;
    int x = v;
    for (int o = 1; o < 32; o <<= 1) {
        int t = __shfl_up_sync(0xFFFFFFFFu, x, o);
        if (lane >= o) x += t;
    }
    __shared__ int ws[4];
    if (lane == 31) ws[w] = x;
    __syncthreads();
    int add = 0;
    for (int i = 0; i < w; i++) add += ws[i];
    if (tid < SCAN_BLOCKS) g_bsums[tid] = x + add - v;  // exclusive
}
__global__ void scan3_kernel() {
    int idx = blockIdx.x * 1024 + threadIdx.x;
    if (idx < N_NODES) g_rowptr[idx + 1] += g_bsums[blockIdx.x];
}
__global__ void fill_kernel(const int* __restrict__ src, const int* __restrict__ dst) {
    int e = blockIdx.x * blockDim.x + threadIdx.x;
    if (e < N_EDGES) {
        int d = dst[e];
        int pos = g_rowptr[d] + atomicAdd(&g_fill[d], 1);
        g_csr[pos] = src[e];
    }
}

// ====================== weight pre-transpose ================================
__global__ void wtrans_kernel(const float* __restrict__ Wl0, const float* __restrict__ Wr0,
                              const float* __restrict__ Wl1, const float* __restrict__ Wr1,
                              const float* __restrict__ Wl2, const float* __restrict__ Wr2) {
    int i = blockIdx.x * blockDim.x + threadIdx.x;
    if (i < 256 * 256) {                       // wt0: N=256, K=256
        int n = i >> 8, k = i & 255;
        g_wt0[i] = (n < 128) ? Wl0[k * 128 + n] : Wr0[k * 128 + (n - 128)];
    }
    if (i < 256 * 128) {                       // wt1: N=256, K=128
        int n = i >> 7, k = i & 127;
        g_wt1[i] = (n < 128) ? Wl1[k * 128 + n] : Wr1[k * 128 + (n - 128)];
    }
    if (i < 128 * 128) {                       // wt2: N=128, K=128
        int n = i >> 7, k = i & 127;
        g_wt2[i] = (n < 64) ? Wl2[k * 64 + n] : Wr2[k * 64 + (n - 64)];
    }
}

// ====================== mma.sync tf32 GEMM ==================================
// Computes Y[M, NN] = A[M, KT] * BT[NN, KT]^T, then splits columns:
//   cols [0, SPLIT)      -> Yl, written as fp16 to ylh  (ld = SPLIT)
//   cols [SPLIT, NN)     -> Yr, written as fp32 to yr   (ld = SPLIT)
// CTA tile 128x128 (blockIdx.y picks col tile). 8 warps of 32x64.
// K chunked KC=32 in SMEM, double-buffered via register prefetch.
#define KC 32
#define SM_STRIDE 36                        // floats; (4r+k)%32 covers all banks
#define BUF_FLOATS (128 * SM_STRIDE)        // 4608 per matrix
#define STAGE_FLOATS (2 * BUF_FLOATS)       // A + B per stage

template <int KT, int NN>
__global__ void __launch_bounds__(256, 1)
gemm_mma_kernel(const float* __restrict__ A, const float* __restrict__ BT,
                __half* __restrict__ ylh, float* __restrict__ yr, int M) {
    constexpr int SPLIT = NN / 2;
    extern __shared__ float sm[];
    const int tid = threadIdx.x;
    const int wid = tid >> 5;
    const int lane = tid & 31;
    const int warpM = wid & 3;
    const int warpN = wid >> 2;
    const int rowBase = blockIdx.x * 128;
    const int colBase = blockIdx.y * 128;
    constexpr int NC = KT / KC;

    float acc[2][8][4];
#pragma unroll
    for (int mt = 0; mt < 2; mt++)
#pragma unroll
        for (int nt = 0; nt < 8; nt++)
#pragma unroll
            for (int q = 0; q < 4; q++) acc[mt][nt][q] = 0.f;

    const int ldRow = tid >> 3;          // 0..31 (+i*32)
    const int ldKq  = (tid & 7) * 4;     // k offset in floats

    float4 ra[4], rb[4];
#pragma unroll
    for (int i = 0; i < 4; i++) {
        int r = ldRow + i * 32;
        int gr = rowBase + r;
        ra[i] = (gr < M) ? *(const float4*)(A + (size_t)gr * KT + ldKq)
                         : make_float4(0.f, 0.f, 0.f, 0.f);
        int gn = colBase + r;
        rb[i] = *(const float4*)(BT + (size_t)gn * KT + ldKq);
    }
    {
        float* As = sm;
        float* Bs = sm + BUF_FLOATS;
#pragma unroll
        for (int i = 0; i < 4; i++) {
            int r = ldRow + i * 32;
            float4 va = ra[i], vb = rb[i];
            va.x = to_tf32(va.x); va.y = to_tf32(va.y); va.z = to_tf32(va.z); va.w = to_tf32(va.w);
            vb.x = to_tf32(vb.x); vb.y = to_tf32(vb.y); vb.z = to_tf32(vb.z); vb.w = to_tf32(vb.w);
            *(float4*)(As + r * SM_STRIDE + ldKq) = va;
            *(float4*)(Bs + r * SM_STRIDE + ldKq) = vb;
        }
    }
    __syncthreads();

    const int aRow = warpM * 32 + (lane >> 2);
    const int aCol = lane & 3;
    const int bRow = warpN * 64 + (lane >> 2);

    for (int c = 0; c < NC; c++) {
        if (c + 1 < NC) {
            int kBase = (c + 1) * KC;
#pragma unroll
            for (int i = 0; i < 4; i++) {
                int r = ldRow + i * 32;
                int gr = rowBase + r;
                ra[i] = (gr < M) ? *(const float4*)(A + (size_t)gr * KT + kBase + ldKq)
                                 : make_float4(0.f, 0.f, 0.f, 0.f);
                int gn = colBase + r;
                rb[i] = *(const float4*)(BT + (size_t)gn * KT + kBase + ldKq);
            }
        }
        const float* As = sm + (c & 1) * STAGE_FLOATS;
        const float* Bs = As + BUF_FLOATS;
#pragma unroll
        for (int ks = 0; ks < KC / 8; ks++) {
            uint32_t af[2][4];
            uint32_t bf[8][2];
#pragma unroll
            for (int mt = 0; mt < 2; mt++) {
                const float* p = As + (aRow + mt * 16) * SM_STRIDE + ks * 8 + aCol;
                af[mt][0] = __float_as_uint(p[0]);
                af[mt][1] = __float_as_uint(p[8 * SM_STRIDE]);
                af[mt][2] = __float_as_uint(p[4]);
                af[mt][3] = __float_as_uint(p[8 * SM_STRIDE + 4]);
            }
#pragma unroll
            for (int nt = 0; nt < 8; nt++) {
                const float* p = Bs + (bRow + nt * 8) * SM_STRIDE + ks * 8 + aCol;
                bf[nt][0] = __float_as_uint(p[0]);
                bf[nt][1] = __float_as_uint(p[4]);
            }
#pragma unroll
            for (int mt = 0; mt < 2; mt++)
#pragma unroll
                for (int nt = 0; nt < 8; nt++)
                    mma_tf32(acc[mt][nt], af[mt], bf[nt]);
        }
        if (c + 1 < NC) {
            float* Asn = sm + ((c + 1) & 1) * STAGE_FLOATS;
            float* Bsn = Asn + BUF_FLOATS;
#pragma unroll
            for (int i = 0; i < 4; i++) {
                int r = ldRow + i * 32;
                float4 va = ra[i], vb = rb[i];
                va.x = to_tf32(va.x); va.y = to_tf32(va.y); va.z = to_tf32(va.z); va.w = to_tf32(va.w);
                vb.x = to_tf32(vb.x); vb.y = to_tf32(vb.y); vb.z = to_tf32(vb.z); vb.w = to_tf32(vb.w);
                *(float4*)(Asn + r * SM_STRIDE + ldKq) = va;
                *(float4*)(Bsn + r * SM_STRIDE + ldKq) = vb;
            }
            __syncthreads();
        }
    }

    // ---- epilogue: split write (fp16 yl / fp32 yr) ----
#pragma unroll
    for (int mt = 0; mt < 2; mt++) {
        int r0 = rowBase + warpM * 32 + mt * 16 + (lane >> 2);
#pragma unroll
        for (int nt = 0; nt < 8; nt++) {
            int colg = colBase + warpN * 64 + nt * 8 + (lane & 3) * 2;
#pragma unroll
            for (int half = 0; half < 2; half++) {
                int row = r0 + half * 8;
                if (row >= M) continue;
                float c0 = acc[mt][nt][half * 2 + 0];
                float c1 = acc[mt][nt][half * 2 + 1];
                if (colg < SPLIT) {
                    *(__half2*)(ylh + (size_t)row * SPLIT + colg) = __floats2half2_rn(c0, c1);
                } else {
                    *(float2*)(yr + (size_t)row * SPLIT + (colg - SPLIT)) = make_float2(c0, c1);
                }
            }
        }
    }
}

// ====================== aggregation epilogue ================================
// out[i] = mean_{s in nbrs(i)} yl[s] (fp16) + yr[i] (fp32) + b
// One warp per node. C=128: lane covers 4 channels (8B fp16 load / edge-row).
template <bool WPRE, bool WPOST>
__global__ void agg128_kernel(const __half* __restrict__ yl, const float* __restrict__ yr,
                              const float* __restrict__ bias,
                              float* __restrict__ outPre, float* __restrict__ outPost) {
    int warp = (blockIdx.x * blockDim.x + threadIdx.x) >> 5;
    int lane = threadIdx.x & 31;
    if (warp >= N_NODES) return;
    int beg = g_rowptr[warp], end = g_rowptr[warp + 1];
    float ax = 0.f, ay = 0.f, az = 0.f, aw = 0.f;
    int e = beg;
    for (; e + 4 <= end; e += 4) {
        int s0 = g_csr[e], s1 = g_csr[e + 1], s2 = g_csr[e + 2], s3 = g_csr[e + 3];
        uint2 q0 = *(const uint2*)(yl + (size_t)s0 * 128 + lane * 4);
        uint2 q1 = *(const uint2*)(yl + (size_t)s1 * 128 + lane * 4);
        uint2 q2 = *(const uint2*)(yl + (size_t)s2 * 128 + lane * 4);
        uint2 q3 = *(const uint2*)(yl + (size_t)s3 * 128 + lane * 4);
        float2 a0 = __half22float2(*(__half2*)&q0.x), b0 = __half22float2(*(__half2*)&q0.y);
        float2 a1 = __half22float2(*(__half2*)&q1.x), b1 = __half22float2(*(__half2*)&q1.y);
        float2 a2 = __half22float2(*(__half2*)&q2.x), b2 = __half22float2(*(__half2*)&q2.y);
        float2 a3 = __half22float2(*(__half2*)&q3.x), b3 = __half22float2(*(__half2*)&q3.y);
        ax += a0.x + a1.x + a2.x + a3.x;
        ay += a0.y + a1.y + a2.y + a3.y;
        az += b0.x + b1.x + b2.x + b3.x;
        aw += b0.y + b1.y + b2.y + b3.y;
    }
    for (; e < end; e++) {
        int s = g_csr[e];
        uint2 q = *(const uint2*)(yl + (size_t)s * 128 + lane * 4);
        float2 a = __half22float2(*(__half2*)&q.x), b = __half22float2(*(__half2*)&q.y);
        ax += a.x; ay += a.y; az += b.x; aw += b.y;
    }
    int deg = end - beg;
    float inv = 1.f / (float)(deg > 0 ? deg : 1);
    float4 r = *(const float4*)(yr + (size_t)warp * 128 + lane * 4);
    float4 b = *(const float4*)(bias + lane * 4);
    float v0 = ax * inv + r.x + b.x;
    float v1 = ay * inv + r.y + b.y;
    float v2 = az * inv + r.z + b.z;
    float v3 = aw * inv + r.w + b.w;
    size_t o = (size_t)warp * 128 + lane * 4;
    if (WPRE)  *(float4*)(outPre + o)  = make_float4(v0, v1, v2, v3);
    if (WPOST) *(float4*)(outPost + o) = make_float4(fmaxf(v0, 0.f), fmaxf(v1, 0.f),
                                                     fmaxf(v2, 0.f), fmaxf(v3, 0.f));
}

__global__ void agg64_kernel(const __half* __restrict__ yl, const float* __restrict__ yr,
                             const float* __restrict__ bias, float* __restrict__ outPre) {
    int warp = (blockIdx.x * blockDim.x + threadIdx.x) >> 5;
    int lane = threadIdx.x & 31;
    if (warp >= N_NODES) return;
    int beg = g_rowptr[warp], end = g_rowptr[warp + 1];
    float ax = 0.f, ay = 0.f;
    int e = beg;
    for (; e + 4 <= end; e += 4) {
        int s0 = g_csr[e], s1 = g_csr[e + 1], s2 = g_csr[e + 2], s3 = g_csr[e + 3];
        uint32_t q0 = *(const uint32_t*)(yl + (size_t)s0 * 64 + lane * 2);
        uint32_t q1 = *(const uint32_t*)(yl + (size_t)s1 * 64 + lane * 2);
        uint32_t q2 = *(const uint32_t*)(yl + (size_t)s2 * 64 + lane * 2);
        uint32_t q3 = *(const uint32_t*)(yl + (size_t)s3 * 64 + lane * 2);
        float2 a0 = __half22float2(*(__half2*)&q0);
        float2 a1 = __half22float2(*(__half2*)&q1);
        float2 a2 = __half22float2(*(__half2*)&q2);
        float2 a3 = __half22float2(*(__half2*)&q3);
        ax += a0.x + a1.x + a2.x + a3.x;
        ay += a0.y + a1.y + a2.y + a3.y;
    }
    for (; e < end; e++) {
        int s = g_csr[e];
        uint32_t q = *(const uint32_t*)(yl + (size_t)s * 64 + lane * 2);
        float2 a = __half22float2(*(__half2*)&q);
        ax += a.x; ay += a.y;
    }
    int deg = end - beg;
    float inv = 1.f / (float)(deg > 0 ? deg : 1);
    float2 r = *(const float2*)(yr + (size_t)warp * 64 + lane * 2);
    float2 b = *(const float2*)(bias + lane * 2);
    float v0 = ax * inv + r.x + b.x;
    float v1 = ay * inv + r.y + b.y;
    *(float2*)(outPre + (size_t)warp * 64 + lane * 2) = make_float2(v0, v1);
}

// ====================== host launch =========================================
extern "C" void kernel_launch(void* const* d_in, const int* in_sizes, int n_in,
                              void* d_out, int out_size) {
    const float* x   = (const float*)d_in[0];
    const int*   ei  = (const int*)d_in[1];
    const float* Wl0 = (const float*)d_in[2];
    const float* Wr0 = (const float*)d_in[3];
    const float* b0  = (const float*)d_in[4];
    const float* Wl1 = (const float*)d_in[5];
    const float* Wr1 = (const float*)d_in[6];
    const float* b1  = (const float*)d_in[7];
    const float* Wl2 = (const float*)d_in[8];
    const float* Wr2 = (const float*)d_in[9];
    const float* b2  = (const float*)d_in[10];

    const int* src = ei;
    const int* dst = ei + N_EDGES;

    float* out_final = (float*)d_out;                       // [N,64]
    float* out_pre1  = out_final + (size_t)N_NODES * 64;    // [N,128] pre-relu layer1
    float* out_g     = out_pre1 + (size_t)N_NODES * 128;    // [N,128] relu(layer1)

    __half* ylh; float *yrp, *h1ptr, *wt0, *wt1, *wt2;
    cudaGetSymbolAddress((void**)&ylh, g_ylh);
    cudaGetSymbolAddress((void**)&yrp, g_yr);
    cudaGetSymbolAddress((void**)&h1ptr, g_h1);
    cudaGetSymbolAddress((void**)&wt0, g_wt0);
    cudaGetSymbolAddress((void**)&wt1, g_wt1);
    cudaGetSymbolAddress((void**)&wt2, g_wt2);

    constexpr int SMEM_GEMM = 2 * STAGE_FLOATS * 4;   // 73728 bytes
    cudaFuncSetAttribute(gemm_mma_kernel<256, 256>,
                         cudaFuncAttributeMaxDynamicSharedMemorySize, SMEM_GEMM);
    cudaFuncSetAttribute(gemm_mma_kernel<128, 256>,
                         cudaFuncAttributeMaxDynamicSharedMemorySize, SMEM_GEMM);
    cudaFuncSetAttribute(gemm_mma_kernel<128, 128>,
                         cudaFuncAttributeMaxDynamicSharedMemorySize, SMEM_GEMM);

    // CSR build + weight transpose
    zero_kernel<<<(N_NODES + 1023) / 1024, 1024>>>();
    deg_kernel<<<(N_EDGES + 255) / 256, 256>>>(dst);
    scan1_kernel<<<SCAN_BLOCKS, 1024>>>();
    scan2_kernel<<<1, 128>>>();
    scan3_kernel<<<SCAN_BLOCKS, 1024>>>();
    fill_kernel<<<(N_EDGES + 255) / 256, 256>>>(src, dst);
    wtrans_kernel<<<(256 * 256 + 255) / 256, 256>>>(Wl0, Wr0, Wl1, Wr1, Wl2, Wr2);

    const int aggGrid = (N_NODES * 32 + 255) / 256;
    const int gemmGridX = (N_NODES + 127) / 128;   // 782

    // Layer 0: [yl|yr] = x@[Wl0|Wr0]; h1 = relu(mean(yl) + yr + b0)
    gemm_mma_kernel<256, 256><<<dim3(gemmGridX, 2), 256, SMEM_GEMM>>>(x, wt0, ylh, yrp, N_NODES);
    agg128_kernel<false, true><<<aggGrid, 256>>>(ylh, yrp, b0, nullptr, h1ptr);

    // Layer 1: out_pre1 = mean(yl) + yr + b1; g = relu(out_pre1)
    gemm_mma_kernel<128, 256><<<dim3(gemmGridX, 2), 256, SMEM_GEMM>>>(h1ptr, wt1, ylh, yrp, N_NODES);
    agg128_kernel<true, true><<<aggGrid, 256>>>(ylh, yrp, b1, out_pre1, out_g);

    // Layer 2: x_final = mean(yl) + yr + b2 (no relu)
    gemm_mma_kernel<128, 128><<<dim3(gemmGridX, 1), 256, SMEM_GEMM>>>(out_g, wt2, ylh, yrp, N_NODES);
    agg64_kernel<<<aggGrid, 256>>>(ylh, yrp, b2, out_final);
}

// round 7
// speedup vs baseline: 2.4523x; 1.2567x over previous
#include <cuda_runtime.h>
#include <cuda_fp16.h>
#include <cstdint>

#define N_NODES 100000
#define N_EDGES 1600000
#define SCAN_BLOCKS 98   // ceil(100000/1024)

// ====================== helpers =============================================
__device__ __forceinline__ void mma_f16(float c[4], const uint32_t a[4], const uint32_t b[2]) {
    asm volatile(
        "mma.sync.aligned.m16n8k16.row.col.f32.f16.f16.f32 "
        "{%0,%1,%2,%3}, {%4,%5,%6,%7}, {%8,%9}, {%0,%1,%2,%3};"
        : "+f"(c[0]), "+f"(c[1]), "+f"(c[2]), "+f"(c[3])
        : "r"(a[0]), "r"(a[1]), "r"(a[2]), "r"(a[3]), "r"(b[0]), "r"(b[1]));
}
__device__ __forceinline__ uint32_t pack_h2(float a, float b) {
    __half2 h = __floats2half2_rn(a, b);
    return *(uint32_t*)&h;
}

// ====================== scratch globals =====================================
__device__ __half g_ylh[(size_t)N_NODES * 128];  // yl half (fp16, gathered side)
__device__ float  g_yr[(size_t)N_NODES * 128];   // yr half (fp32, exact side)
__device__ float  g_h1[(size_t)N_NODES * 128];   // relu(layer0 out)
__device__ int    g_deg[N_NODES];
__device__ int    g_fill[N_NODES];
__device__ int    g_rowptr[N_NODES + 1];
__device__ int    g_csr[N_EDGES];
__device__ int    g_bsums[SCAN_BLOCKS];
__device__ float  g_wt0[256 * 256];   // [n][k]: n<128 -> Wl0[:,n], else Wr0[:,n-128]
__device__ float  g_wt1[256 * 128];
__device__ float  g_wt2[128 * 128];

// ====================== CSR build ===========================================
__global__ void zero_kernel() {
    int i = blockIdx.x * blockDim.x + threadIdx.x;
    if (i < N_NODES) { g_deg[i] = 0; g_fill[i] = 0; }
}
__global__ void deg_kernel(const int* __restrict__ dst) {
    int e = blockIdx.x * blockDim.x + threadIdx.x;
    if (e < N_EDGES) atomicAdd(&g_deg[dst[e]], 1);
}
__global__ void scan1_kernel() {
    __shared__ int s[1024];
    int tid = threadIdx.x;
    int idx = blockIdx.x * 1024 + tid;
    int v = (idx < N_NODES) ? g_deg[idx] : 0;
    s[tid] = v;
    __syncthreads();
    for (int off = 1; off < 1024; off <<= 1) {
        int t = 0;
        if (tid >= off) t = s[tid - off];
        __syncthreads();
        s[tid] += t;
        __syncthreads();
    }
    if (idx < N_NODES) g_rowptr[idx + 1] = s[tid];
    if (tid == 1023) g_bsums[blockIdx.x] = s[tid];
    if (idx == 0) g_rowptr[0] = 0;
}
__global__ void scan2_kernel() {       // 128-thread shfl scan over SCAN_BLOCKS sums
    int tid = threadIdx.x;
    int v = (tid < SCAN_BLOCKS) ? g_bsums[tid] : 0;
    int lane = tid & 31, w = tid >> 5;
    int x = v;
    for (int o = 1; o < 32; o <<= 1) {
        int t = __shfl_up_sync(0xFFFFFFFFu, x, o);
        if (lane >= o) x += t;
    }
    __shared__ int ws[4];
    if (lane == 31) ws[w] = x;
    __syncthreads();
    int add = 0;
    for (int i = 0; i < w; i++) add += ws[i];
    if (tid < SCAN_BLOCKS) g_bsums[tid] = x + add - v;  // exclusive
}
__global__ void scan3_kernel() {
    int idx = blockIdx.x * 1024 + threadIdx.x;
    if (idx < N_NODES) g_rowptr[idx + 1] += g_bsums[blockIdx.x];
}
__global__ void fill_kernel(const int* __restrict__ src, const int* __restrict__ dst) {
    int e = blockIdx.x * blockDim.x + threadIdx.x;
    if (e < N_EDGES) {
        int d = dst[e];
        int pos = g_rowptr[d] + atomicAdd(&g_fill[d], 1);
        g_csr[pos] = src[e];
    }
}

// ====================== weight pre-transpose ================================
__global__ void wtrans_kernel(const float* __restrict__ Wl0, const float* __restrict__ Wr0,
                              const float* __restrict__ Wl1, const float* __restrict__ Wr1,
                              const float* __restrict__ Wl2, const float* __restrict__ Wr2) {
    int i = blockIdx.x * blockDim.x + threadIdx.x;
    if (i < 256 * 256) {                       // wt0: N=256, K=256
        int n = i >> 8, k = i & 255;
        g_wt0[i] = (n < 128) ? Wl0[k * 128 + n] : Wr0[k * 128 + (n - 128)];
    }
    if (i < 256 * 128) {                       // wt1: N=256, K=128
        int n = i >> 7, k = i & 127;
        g_wt1[i] = (n < 128) ? Wl1[k * 128 + n] : Wr1[k * 128 + (n - 128)];
    }
    if (i < 128 * 128) {                       // wt2: N=128, K=128
        int n = i >> 7, k = i & 127;
        g_wt2[i] = (n < 64) ? Wl2[k * 64 + n] : Wr2[k * 64 + (n - 64)];
    }
}

// ====================== mma.sync fp16 GEMM ==================================
// Y[M, NN] = A[M, KT] * BT[NN, KT]^T, cols [0,SPLIT) -> fp16 ylh, rest -> fp32 yr.
// CTA tile 128x128 (blockIdx.y picks col tile). 8 warps of 32x64.
// Operands converted fp32->fp16 on the SMEM store path (same 11-bit mantissa
// as tf32). K chunked KC=32 in SMEM, double-buffered via register prefetch.
#define KC 32
#define SH 40                              // halves per row; rows hit distinct banks
#define BUF_H (128 * SH)                   // 5120 halves (10240 B) per matrix
#define STAGE_H (2 * BUF_H)

template <int KT, int NN>
__global__ void __launch_bounds__(256)
gemm_mma_kernel(const float* __restrict__ A, const float* __restrict__ BT,
                __half* __restrict__ ylh, float* __restrict__ yr, int M) {
    constexpr int SPLIT = NN / 2;
    __shared__ __half sm[2 * STAGE_H];     // 40960 bytes (static)
    const int tid = threadIdx.x;
    const int wid = tid >> 5;
    const int lane = tid & 31;
    const int warpM = wid & 3;
    const int warpN = wid >> 2;
    const int rowBase = blockIdx.x * 128;
    const int colBase = blockIdx.y * 128;
    constexpr int NC = KT / KC;

    float acc[2][8][4];
#pragma unroll
    for (int mt = 0; mt < 2; mt++)
#pragma unroll
        for (int nt = 0; nt < 8; nt++)
#pragma unroll
            for (int q = 0; q < 4; q++) acc[mt][nt][q] = 0.f;

    const int ldRow = tid >> 3;          // 0..31 (+i*32)
    const int ldKq  = (tid & 7) * 4;     // k offset (floats/halves)

    float4 ra[4], rb[4];
#pragma unroll
    for (int i = 0; i < 4; i++) {
        int r = ldRow + i * 32;
        int gr = rowBase + r;
        ra[i] = (gr < M) ? *(const float4*)(A + (size_t)gr * KT + ldKq)
                         : make_float4(0.f, 0.f, 0.f, 0.f);
        rb[i] = *(const float4*)(BT + (size_t)(colBase + r) * KT + ldKq);
    }
    {
        __half* As = sm;
        __half* Bs = sm + BUF_H;
#pragma unroll
        for (int i = 0; i < 4; i++) {
            int r = ldRow + i * 32;
            *(uint2*)(As + r * SH + ldKq) = make_uint2(pack_h2(ra[i].x, ra[i].y),
                                                       pack_h2(ra[i].z, ra[i].w));
            *(uint2*)(Bs + r * SH + ldKq) = make_uint2(pack_h2(rb[i].x, rb[i].y),
                                                       pack_h2(rb[i].z, rb[i].w));
        }
    }
    __syncthreads();

    const int aRowB = warpM * 32 + (lane >> 2);
    const int aCol2 = (lane & 3) * 2;
    const int bRowB = warpN * 64 + (lane >> 2);

    for (int c = 0; c < NC; c++) {
        if (c + 1 < NC) {
            int kBase = (c + 1) * KC;
#pragma unroll
            for (int i = 0; i < 4; i++) {
                int r = ldRow + i * 32;
                int gr = rowBase + r;
                ra[i] = (gr < M) ? *(const float4*)(A + (size_t)gr * KT + kBase + ldKq)
                                 : make_float4(0.f, 0.f, 0.f, 0.f);
                rb[i] = *(const float4*)(BT + (size_t)(colBase + r) * KT + kBase + ldKq);
            }
        }
        const __half* As = sm + (c & 1) * STAGE_H;
        const __half* Bs = As + BUF_H;
#pragma unroll
        for (int ks = 0; ks < KC / 16; ks++) {
            const int k0 = ks * 16 + aCol2;
            uint32_t af[2][4];
            uint32_t bf[8][2];
#pragma unroll
            for (int mt = 0; mt < 2; mt++) {
                const __half* p = As + (aRowB + mt * 16) * SH + k0;
                af[mt][0] = *(const uint32_t*)(p);
                af[mt][1] = *(const uint32_t*)(p + 8 * SH);
                af[mt][2] = *(const uint32_t*)(p + 8);
                af[mt][3] = *(const uint32_t*)(p + 8 * SH + 8);
            }
#pragma unroll
            for (int nt = 0; nt < 8; nt++) {
                const __half* p = Bs + (bRowB + nt * 8) * SH + k0;
                bf[nt][0] = *(const uint32_t*)(p);
                bf[nt][1] = *(const uint32_t*)(p + 8);
            }
#pragma unroll
            for (int mt = 0; mt < 2; mt++)
#pragma unroll
                for (int nt = 0; nt < 8; nt++)
                    mma_f16(acc[mt][nt], af[mt], bf[nt]);
        }
        if (c + 1 < NC) {
            __half* Asn = sm + ((c + 1) & 1) * STAGE_H;
            __half* Bsn = Asn + BUF_H;
#pragma unroll
            for (int i = 0; i < 4; i++) {
                int r = ldRow + i * 32;
                *(uint2*)(Asn + r * SH + ldKq) = make_uint2(pack_h2(ra[i].x, ra[i].y),
                                                            pack_h2(ra[i].z, ra[i].w));
                *(uint2*)(Bsn + r * SH + ldKq) = make_uint2(pack_h2(rb[i].x, rb[i].y),
                                                            pack_h2(rb[i].z, rb[i].w));
            }
            __syncthreads();
        }
    }

    // ---- epilogue: split write (fp16 yl / fp32 yr) ----
#pragma unroll
    for (int mt = 0; mt < 2; mt++) {
        int r0 = rowBase + warpM * 32 + mt * 16 + (lane >> 2);
#pragma unroll
        for (int nt = 0; nt < 8; nt++) {
            int colg = colBase + warpN * 64 + nt * 8 + (lane & 3) * 2;
#pragma unroll
            for (int hf = 0; hf < 2; hf++) {
                int row = r0 + hf * 8;
                if (row >= M) continue;
                float c0 = acc[mt][nt][hf * 2 + 0];
                float c1 = acc[mt][nt][hf * 2 + 1];
                if (colg < SPLIT) {
                    *(__half2*)(ylh + (size_t)row * SPLIT + colg) = __floats2half2_rn(c0, c1);
                } else {
                    *(float2*)(yr + (size_t)row * SPLIT + (colg - SPLIT)) = make_float2(c0, c1);
                }
            }
        }
    }
}

// ====================== aggregation epilogue ================================
template <bool WPRE, bool WPOST>
__global__ void agg128_kernel(const __half* __restrict__ yl, const float* __restrict__ yr,
                              const float* __restrict__ bias,
                              float* __restrict__ outPre, float* __restrict__ outPost) {
    int warp = (blockIdx.x * blockDim.x + threadIdx.x) >> 5;
    int lane = threadIdx.x & 31;
    if (warp >= N_NODES) return;
    int beg = g_rowptr[warp], end = g_rowptr[warp + 1];
    float ax = 0.f, ay = 0.f, az = 0.f, aw = 0.f;
    int e = beg;
    for (; e + 4 <= end; e += 4) {
        int s0 = g_csr[e], s1 = g_csr[e + 1], s2 = g_csr[e + 2], s3 = g_csr[e + 3];
        uint2 q0 = *(const uint2*)(yl + (size_t)s0 * 128 + lane * 4);
        uint2 q1 = *(const uint2*)(yl + (size_t)s1 * 128 + lane * 4);
        uint2 q2 = *(const uint2*)(yl + (size_t)s2 * 128 + lane * 4);
        uint2 q3 = *(const uint2*)(yl + (size_t)s3 * 128 + lane * 4);
        float2 a0 = __half22float2(*(__half2*)&q0.x), b0 = __half22float2(*(__half2*)&q0.y);
        float2 a1 = __half22float2(*(__half2*)&q1.x), b1 = __half22float2(*(__half2*)&q1.y);
        float2 a2 = __half22float2(*(__half2*)&q2.x), b2 = __half22float2(*(__half2*)&q2.y);
        float2 a3 = __half22float2(*(__half2*)&q3.x), b3 = __half22float2(*(__half2*)&q3.y);
        ax += a0.x + a1.x + a2.x + a3.x;
        ay += a0.y + a1.y + a2.y + a3.y;
        az += b0.x + b1.x + b2.x + b3.x;
        aw += b0.y + b1.y + b2.y + b3.y;
    }
    for (; e < end; e++) {
        int s = g_csr[e];
        uint2 q = *(const uint2*)(yl + (size_t)s * 128 + lane * 4);
        float2 a = __half22float2(*(__half2*)&q.x), b = __half22float2(*(__half2*)&q.y);
        ax += a.x; ay += a.y; az += b.x; aw += b.y;
    }
    int deg = end - beg;
    float inv = 1.f / (float)(deg > 0 ? deg : 1);
    float4 r = *(const float4*)(yr + (size_t)warp * 128 + lane * 4);
    float4 b = *(const float4*)(bias + lane * 4);
    float v0 = ax * inv + r.x + b.x;
    float v1 = ay * inv + r.y + b.y;
    float v2 = az * inv + r.z + b.z;
    float v3 = aw * inv + r.w + b.w;
    size_t o = (size_t)warp * 128 + lane * 4;
    if (WPRE)  *(float4*)(outPre + o)  = make_float4(v0, v1, v2, v3);
    if (WPOST) *(float4*)(outPost + o) = make_float4(fmaxf(v0, 0.f), fmaxf(v1, 0.f),
                                                     fmaxf(v2, 0.f), fmaxf(v3, 0.f));
}

__global__ void agg64_kernel(const __half* __restrict__ yl, const float* __restrict__ yr,
                             const float* __restrict__ bias, float* __restrict__ outPre) {
    int warp = (blockIdx.x * blockDim.x + threadIdx.x) >> 5;
    int lane = threadIdx.x & 31;
    if (warp >= N_NODES) return;
    int beg = g_rowptr[warp], end = g_rowptr[warp + 1];
    float ax = 0.f, ay = 0.f;
    int e = beg;
    for (; e + 4 <= end; e += 4) {
        int s0 = g_csr[e], s1 = g_csr[e + 1], s2 = g_csr[e + 2], s3 = g_csr[e + 3];
        uint32_t q0 = *(const uint32_t*)(yl + (size_t)s0 * 64 + lane * 2);
        uint32_t q1 = *(const uint32_t*)(yl + (size_t)s1 * 64 + lane * 2);
        uint32_t q2 = *(const uint32_t*)(yl + (size_t)s2 * 64 + lane * 2);
        uint32_t q3 = *(const uint32_t*)(yl + (size_t)s3 * 64 + lane * 2);
        float2 a0 = __half22float2(*(__half2*)&q0);
        float2 a1 = __half22float2(*(__half2*)&q1);
        float2 a2 = __half22float2(*(__half2*)&q2);
        float2 a3 = __half22float2(*(__half2*)&q3);
        ax += a0.x + a1.x + a2.x + a3.x;
        ay += a0.y + a1.y + a2.y + a3.y;
    }
    for (; e < end; e++) {
        int s = g_csr[e];
        uint32_t q = *(const uint32_t*)(yl + (size_t)s * 64 + lane * 2);
        float2 a = __half22float2(*(__half2*)&q);
        ax += a.x; ay += a.y;
    }
    int deg = end - beg;
    float inv = 1.f / (float)(deg > 0 ? deg : 1);
    float2 r = *(const float2*)(yr + (size_t)warp * 64 + lane * 2);
    float2 b = *(const float2*)(bias + lane * 2);
    float v0 = ax * inv + r.x + b.x;
    float v1 = ay * inv + r.y + b.y;
    *(float2*)(outPre + (size_t)warp * 64 + lane * 2) = make_float2(v0, v1);
}

// ====================== host launch =========================================
extern "C" void kernel_launch(void* const* d_in, const int* in_sizes, int n_in,
                              void* d_out, int out_size) {
    const float* x   = (const float*)d_in[0];
    const int*   ei  = (const int*)d_in[1];
    const float* Wl0 = (const float*)d_in[2];
    const float* Wr0 = (const float*)d_in[3];
    const float* b0  = (const float*)d_in[4];
    const float* Wl1 = (const float*)d_in[5];
    const float* Wr1 = (const float*)d_in[6];
    const float* b1  = (const float*)d_in[7];
    const float* Wl2 = (const float*)d_in[8];
    const float* Wr2 = (const float*)d_in[9];
    const float* b2  = (const float*)d_in[10];

    const int* src = ei;
    const int* dst = ei + N_EDGES;

    float* out_final = (float*)d_out;                       // [N,64]
    float* out_pre1  = out_final + (size_t)N_NODES * 64;    // [N,128] pre-relu layer1
    float* out_g     = out_pre1 + (size_t)N_NODES * 128;    // [N,128] relu(layer1)

    __half* ylh; float *yrp, *h1ptr, *wt0, *wt1, *wt2;
    cudaGetSymbolAddress((void**)&ylh, g_ylh);
    cudaGetSymbolAddress((void**)&yrp, g_yr);
    cudaGetSymbolAddress((void**)&h1ptr, g_h1);
    cudaGetSymbolAddress((void**)&wt0, g_wt0);
    cudaGetSymbolAddress((void**)&wt1, g_wt1);
    cudaGetSymbolAddress((void**)&wt2, g_wt2);

    // Side stream + fork/join events, created once on the (uncaptured)
    // correctness call; reused inside graph capture (standard fork-join).
    static cudaStream_t s_side = nullptr;
    static cudaEvent_t evFork = nullptr, evJoin = nullptr;
    if (s_side == nullptr) {
        cudaStreamCreateWithFlags(&s_side, cudaStreamNonBlocking);
        cudaEventCreateWithFlags(&evFork, cudaEventDisableTiming);
        cudaEventCreateWithFlags(&evJoin, cudaEventDisableTiming);
    }

    // ---- fork: CSR build on side stream ----
    cudaEventRecord(evFork, 0);
    cudaStreamWaitEvent(s_side, evFork, 0);
    zero_kernel<<<(N_NODES + 1023) / 1024, 1024, 0, s_side>>>();
    deg_kernel<<<(N_EDGES + 255) / 256, 256, 0, s_side>>>(dst);
    scan1_kernel<<<SCAN_BLOCKS, 1024, 0, s_side>>>();
    scan2_kernel<<<1, 128, 0, s_side>>>();
    scan3_kernel<<<SCAN_BLOCKS, 1024, 0, s_side>>>();
    fill_kernel<<<(N_EDGES + 255) / 256, 256, 0, s_side>>>(src, dst);
    cudaEventRecord(evJoin, s_side);

    // ---- main stream: weights + layer-0 GEMM overlap the CSR build ----
    wtrans_kernel<<<(256 * 256 + 255) / 256, 256>>>(Wl0, Wr0, Wl1, Wr1, Wl2, Wr2);

    const int aggGrid = (N_NODES * 32 + 255) / 256;
    const int gemmGridX = (N_NODES + 127) / 128;   // 782

    // Layer 0: [yl|yr] = x@[Wl0|Wr0]; h1 = relu(mean(yl) + yr + b0)
    gemm_mma_kernel<256, 256><<<dim3(gemmGridX, 2), 256>>>(x, wt0, ylh, yrp, N_NODES);
    cudaStreamWaitEvent(0, evJoin, 0);   // agg needs the CSR
    agg128_kernel<false, true><<<aggGrid, 256>>>(ylh, yrp, b0, nullptr, h1ptr);

    // Layer 1: out_pre1 = mean(yl) + yr + b1; g = relu(out_pre1)
    gemm_mma_kernel<128, 256><<<dim3(gemmGridX, 2), 256>>>(h1ptr, wt1, ylh, yrp, N_NODES);
    agg128_kernel<true, true><<<aggGrid, 256>>>(ylh, yrp, b1, out_pre1, out_g);

    // Layer 2: x_final = mean(yl) + yr + b2 (no relu)
    gemm_mma_kernel<128, 128><<<dim3(gemmGridX, 1), 256>>>(out_g, wt2, ylh, yrp, N_NODES);
    agg64_kernel<<<aggGrid, 256>>>(ylh, yrp, b2, out_final);
}